// round 5
// baseline (speedup 1.0000x reference)
#include <cuda_runtime.h>
#include <cuda_bf16.h>

// Inputs (metadata order; int64 arrays delivered as int32 by the harness):
//   d_in[0] vertex_attr : float32 [1000000, 2]
//   d_in[1] edgeij_pair : int32   [2, 16000000]   (row 0 = source indices, contiguous)
//   d_in[2] edge_attr   : float32 [16000000, 2]
//   d_in[3] g           : float32 [1,1]          (unused)
//   d_in[4] batch       : int32   [1000000]      (unused)
// Output: float32 [1000000, 3] = concat(b_i, x_i, b_i - segsum(c_ij over edge src))

#define NV_MAX 1000000

// Zero-initialized at module load. finalize_kernel re-zeroes it after reading,
// so the "cbar == 0 on entry" invariant holds for every launch/replay.
__device__ float g_cbar[NV_MAX];

// 8 edges per thread: 2x int4 index loads + 4x float4 attr loads (streaming,
// evict-first so the L2 keeps g_cbar resident), then 8 no-return atomics.
__global__ void scatter_kernel(const int4* __restrict__ idx4,
                               const float4* __restrict__ ea4,
                               float* __restrict__ cbar,
                               int n_oct) {
    int t = blockIdx.x * blockDim.x + threadIdx.x;
    if (t >= n_oct) return;

    int4 ia = __ldcs(idx4 + 2 * t);        // edges 8t .. 8t+3
    int4 ib = __ldcs(idx4 + 2 * t + 1);    // edges 8t+4 .. 8t+7

    const float4* ep = ea4 + 4 * t;
    float4 e0 = __ldcs(ep + 0);            // (c0a,c1a, c0b,c1b) edges 8t,8t+1
    float4 e1 = __ldcs(ep + 1);
    float4 e2 = __ldcs(ep + 2);
    float4 e3 = __ldcs(ep + 3);

    atomicAdd(cbar + ia.x, e0.y);
    atomicAdd(cbar + ia.y, e0.w);
    atomicAdd(cbar + ia.z, e1.y);
    atomicAdd(cbar + ia.w, e1.w);
    atomicAdd(cbar + ib.x, e2.y);
    atomicAdd(cbar + ib.y, e2.w);
    atomicAdd(cbar + ib.z, e3.y);
    atomicAdd(cbar + ib.w, e3.w);
}

// 4 vertices per thread, fully vectorized 16B traffic; re-zeroes cbar for the
// next launch (restores the module-load-time zero state).
__global__ void finalize_kernel(const float4* __restrict__ va4,
                                float4* __restrict__ cbar4,
                                float4* __restrict__ out4,
                                int n_quads) {
    int t = blockIdx.x * blockDim.x + threadIdx.x;
    if (t >= n_quads) return;

    float4 v01 = va4[2 * t];        // (b0,x0,b1,x1)
    float4 v23 = va4[2 * t + 1];    // (b2,x2,b3,x3)
    float4 c   = cbar4[t];          // (c0,c1,c2,c3)

    float r0 = v01.x - c.x;
    float r1 = v01.z - c.y;
    float r2 = v23.x - c.z;
    float r3 = v23.z - c.w;

    out4[3 * t + 0] = make_float4(v01.x, v01.y, r0, v01.z);
    out4[3 * t + 1] = make_float4(v01.w, r1, v23.x, v23.y);
    out4[3 * t + 2] = make_float4(r2, v23.z, v23.w, r3);

    cbar4[t] = make_float4(0.f, 0.f, 0.f, 0.f);
}

extern "C" void kernel_launch(void* const* d_in, const int* in_sizes, int n_in,
                              void* d_out, int out_size) {
    const float4* vertex_attr = (const float4*)d_in[0];
    const int4*   edge_src    = (const int4*)d_in[1];   // row 0 of edgeij_pair (int32)
    const float4* edge_attr   = (const float4*)d_in[2];
    float4*       out         = (float4*)d_out;

    const int n_vertices = in_sizes[0] / 2;
    const int n_edges    = in_sizes[2] / 2;

    float* cbar;
    cudaGetSymbolAddress((void**)&cbar, g_cbar);

    {
        int n_oct = n_edges / 8;            // 16M / 8 = 2M threads
        int threads = 256;
        int blocks = (n_oct + threads - 1) / threads;
        scatter_kernel<<<blocks, threads>>>(edge_src, edge_attr, cbar, n_oct);
    }
    {
        int n_quads = n_vertices / 4;       // 1M / 4 = 250K threads
        int threads = 256;
        int blocks = (n_quads + threads - 1) / threads;
        finalize_kernel<<<blocks, threads>>>(vertex_attr, (float4*)cbar, out, n_quads);
    }
}